// round 15
// baseline (speedup 1.0000x reference)
#include <cuda_runtime.h>
#include <cuda_bf16.h>
#include <cstdint>

// Problem constants (fixed by the reference)
#define N_COLS  22
#define N_PAIRS 231
#define EMB     12
#define N_PRIM  5
#define DVEC    64
#define N_ITEMS 121               // 110 merged pair-duos + 11 singles
#define MERGED_SZ (EMB * EMB * EMB)   // 1728 float2 per item
#define NCHUNK  8
#define ITEMS_PER_CHUNK 16        // ceil(121/8)

// Host-built tables, passed by value (constant bank)
struct K1Tab {
    uchar2 bp[N_ITEMS];          // item -> (pair0, pair1) ; pair1==255 -> single
    uchar2 ij[N_PAIRS];          // pair -> (i, j)
};
struct K2Tab {
    uchar4 cols[N_ITEMS];        // item -> (i, j_a, j_b, 0)
};

// Merged LUT: item m, entry (fi, fa, fb) -> float2  (1.67 MB, L2-resident)
__device__ __align__(16) float g_T2[N_ITEMS * MERGED_SZ * 2];

// ---------------------------------------------------------------------------
// Kernel 1: one block (512 thr) per ITEM. 16 warps compute the item's 1-2
// source tables (quarter-warp unit: lane q=lane>>3 owns fj=4t+q, ql=lane&7
// owns dims 8ql..8ql+7; 3-level xor-shuffle reduce) into SMEM, then all
// threads outer-add into the 1728-entry merged table:
//   M[fi,fa,fb] = s0[fi,fa] + s1[fi,fb]      (s1 = 0 for singles)
// Also zero-initializes out[] (121*512 = 61952 >= outN).
// ---------------------------------------------------------------------------
__global__ __launch_bounds__(512)
void build_lut_kernel(const float* __restrict__ tables,
                      const float* __restrict__ Wsmall,
                      const float* __restrict__ Wconcat,
                      const float* __restrict__ aw,
                      float* __restrict__ out, int outN,
                      const K1Tab tab)
{
    __shared__ float2 s[2][EMB * EMB];   // 2 x 144 float2 = 2.3 KB

    const int tid = threadIdx.x;

    // zero the output buffer (poisoned by harness) for kernel 2's atomics
    {
        const int gz = blockIdx.x * 512 + tid;
        if (gz < outN) out[gz] = 0.0f;
    }

    // zero the staging tables (s[1] must be zero for single items)
    for (int e = tid; e < 2 * EMB * EMB; e += 512)
        ((float2*)s)[e] = make_float2(0.0f, 0.0f);

    const uchar2 bp   = tab.bp[blockIdx.x];
    const bool   has2 = (bp.y != 255);
    __syncthreads();

    const int warp = tid >> 5;
    const int lane = tid & 31;
    const int q    = lane >> 3;          // quarter 0..3
    const int ql   = lane & 7;           // dim-octet within quarter
    const float4* __restrict__ t4 = (const float4*)tables;

    const int nunits = has2 ? 2 * EMB : EMB;   // (pairsel, fi) units
    for (int u = warp; u < nunits; u += 16) {
        const int pairsel = (u >= EMB) ? 1 : 0;
        const int fi      = u - pairsel * EMB;
        const int p       = pairsel ? bp.y : bp.x;
        const int i       = tab.ij[p].x;
        const int j       = tab.ij[p].y;

        // primitive via one ballot (arch_weights is exact one-hot 0/1)
        const bool hot = (lane < N_PRIM) && (__ldg(&aw[p * N_PRIM + lane]) > 0.5f);
        const int  k   = __ffs(__ballot_sync(0xffffffffu, hot)) - 1;

        const float4 PiA = __ldg(&t4[(i * EMB + fi) * 16 + 2 * ql]);
        const float4 PiB = __ldg(&t4[(i * EMB + fi) * 16 + 2 * ql + 1]);

        float4 w0A, w0B, w1A, w1B;       // Q-side weights, o = 0 / 1
        float  pp0 = 0.0f, pp1 = 0.0f;   // reduced P-part for concat
        if (k == 4) {
            const float4* __restrict__ wc = (const float4*)(Wconcat + p * 2 * (2 * DVEC));
            const float4 a0A = __ldg(&wc[2 * ql]),      a0B = __ldg(&wc[2 * ql + 1]);
            const float4 a1A = __ldg(&wc[32 + 2 * ql]), a1B = __ldg(&wc[33 + 2 * ql]);
            w0A = __ldg(&wc[16 + 2 * ql]);  w0B = __ldg(&wc[17 + 2 * ql]);
            w1A = __ldg(&wc[48 + 2 * ql]);  w1B = __ldg(&wc[49 + 2 * ql]);
            pp0 = a0A.x * PiA.x + a0A.y * PiA.y + a0A.z * PiA.z + a0A.w * PiA.w
                + a0B.x * PiB.x + a0B.y * PiB.y + a0B.z * PiB.z + a0B.w * PiB.w;
            pp1 = a1A.x * PiA.x + a1A.y * PiA.y + a1A.z * PiA.z + a1A.w * PiA.w
                + a1B.x * PiB.x + a1B.y * PiB.y + a1B.z * PiB.z + a1B.w * PiB.w;
#pragma unroll
            for (int off = 4; off; off >>= 1) {
                pp0 += __shfl_xor_sync(0xffffffffu, pp0, off);
                pp1 += __shfl_xor_sync(0xffffffffu, pp1, off);
            }
        } else {
            const float4* __restrict__ ws = (const float4*)(Wsmall + (p * 4 + k) * 2 * DVEC);
            w0A = __ldg(&ws[2 * ql]);       w0B = __ldg(&ws[2 * ql + 1]);
            w1A = __ldg(&ws[16 + 2 * ql]);  w1B = __ldg(&ws[17 + 2 * ql]);
        }

#pragma unroll
        for (int t = 0; t < 3; ++t) {
            const int fj = t * 4 + q;
            const float4 QA = __ldg(&t4[(j * EMB + fj) * 16 + 2 * ql]);
            const float4 QB = __ldg(&t4[(j * EMB + fj) * 16 + 2 * ql + 1]);

            float4 zA, zB;
            if (k == 0)      { zA.x = PiA.x + QA.x; zA.y = PiA.y + QA.y; zA.z = PiA.z + QA.z; zA.w = PiA.w + QA.w;
                               zB.x = PiB.x + QB.x; zB.y = PiB.y + QB.y; zB.z = PiB.z + QB.z; zB.w = PiB.w + QB.w; }
            else if (k == 1) { zA.x = PiA.x * QA.x; zA.y = PiA.y * QA.y; zA.z = PiA.z * QA.z; zA.w = PiA.w * QA.w;
                               zB.x = PiB.x * QB.x; zB.y = PiB.y * QB.y; zB.z = PiB.z * QB.z; zB.w = PiB.w * QB.w; }
            else if (k == 2) { zA.x = fmaxf(PiA.x, QA.x); zA.y = fmaxf(PiA.y, QA.y); zA.z = fmaxf(PiA.z, QA.z); zA.w = fmaxf(PiA.w, QA.w);
                               zB.x = fmaxf(PiB.x, QB.x); zB.y = fmaxf(PiB.y, QB.y); zB.z = fmaxf(PiB.z, QB.z); zB.w = fmaxf(PiB.w, QB.w); }
            else if (k == 3) { zA.x = fminf(PiA.x, QA.x); zA.y = fminf(PiA.y, QA.y); zA.z = fminf(PiA.z, QA.z); zA.w = fminf(PiA.w, QA.w);
                               zB.x = fminf(PiB.x, QB.x); zB.y = fminf(PiB.y, QB.y); zB.z = fminf(PiB.z, QB.z); zB.w = fminf(PiB.w, QB.w); }
            else             { zA = QA; zB = QB; }   // concat: Q-part only

            float s0 = zA.x * w0A.x + zA.y * w0A.y + zA.z * w0A.z + zA.w * w0A.w
                     + zB.x * w0B.x + zB.y * w0B.y + zB.z * w0B.z + zB.w * w0B.w;
            float s1 = zA.x * w1A.x + zA.y * w1A.y + zA.z * w1A.z + zA.w * w1A.w
                     + zB.x * w1B.x + zB.y * w1B.y + zB.z * w1B.z + zB.w * w1B.w;
#pragma unroll
            for (int off = 4; off; off >>= 1) {
                s0 += __shfl_xor_sync(0xffffffffu, s0, off);
                s1 += __shfl_xor_sync(0xffffffffu, s1, off);
            }
            if (k == 4) { s0 += pp0; s1 += pp1; }

            if (ql == 0)
                s[pairsel][fi * EMB + fj] = make_float2(s0, s1);
        }
    }
    __syncthreads();

    // merge: M[fi, fa, fb] = s0[fi, fa] + s1[fi, fb]
    float2* __restrict__ T2 = (float2*)g_T2;
    const int base = blockIdx.x * MERGED_SZ;
    for (int e = tid; e < MERGED_SZ; e += 512) {
        const int fi  = e / (EMB * EMB);
        const int rem = e - fi * (EMB * EMB);
        const int fa  = rem / EMB;
        const int fb  = rem - fa * EMB;
        const float2 a = s[0][fi * EMB + fa];
        const float2 b = s[1][fi * EMB + fb];
        T2[base + e] = make_float2(a.x + b.x, a.y + b.y);
    }
}

// ---------------------------------------------------------------------------
// Kernel 2: out[b, :] += sum_{items in chunk} M[item][fi, fa, fb]
// grid = (NCHUNK, B/32), 256 threads (proven winner shape). lane = batch row;
// warp w strides the chunk's <=16 items (<=2 unrolled independent gathers).
// Index = 3 conflict-free LDS + ALU; gather count HALVED vs per-pair LUT.
// Cross-warp SMEM reduce, then atomicAdd (out zeroed by kernel 1).
// ---------------------------------------------------------------------------
__global__ __launch_bounds__(256)
void accumulate_kernel(const int* __restrict__ feats,
                       float* __restrict__ out,
                       int B,
                       const K2Tab tab)
{
    __shared__ int    shf[32][N_COLS + 1];   // stride 23: coprime with 32 banks
    __shared__ float2 shred[8][32];

    const int tid   = threadIdx.x;
    const int lane  = tid & 31;
    const int warp  = tid >> 5;
    const int bbase = blockIdx.y * 32;                   // tile
    const int i0    = blockIdx.x * ITEMS_PER_CHUNK;      // chunk start
    const int i1    = min(N_ITEMS, i0 + ITEMS_PER_CHUNK);

    // coalesced, cooperative load of this block's 32 feats rows
    for (int e = tid; e < 32 * N_COLS; e += 256) {
        const int row = e / N_COLS, col = e - row * N_COLS;
        const int b   = bbase + row;
        shf[row][col] = (b < B) ? feats[b * N_COLS + col] : 0;
    }
    __syncthreads();

    const float2* __restrict__ T2 = (const float2*)g_T2;
    float ax = 0.0f, ay = 0.0f;

#pragma unroll 2
    for (int t = i0 + warp; t < i1; t += 8) {
        const uchar4 c = tab.cols[t];            // constant bank, uniform
        const int fi = shf[lane][c.x];
        const int fa = shf[lane][c.y];
        const int fb = shf[lane][c.z];
        const float2 v = __ldg(&T2[t * MERGED_SZ + fi * (EMB * EMB) + fa * EMB + fb]);
        ax += v.x;
        ay += v.y;
    }

    shred[warp][lane] = make_float2(ax, ay);
    __syncthreads();

    if (warp == 0) {
        float sx = 0.0f, sy = 0.0f;
#pragma unroll
        for (int w = 0; w < 8; ++w) {
            const float2 s = shred[w][lane];
            sx += s.x;
            sy += s.y;
        }
        const int b = bbase + lane;
        if (b < B) {
            atomicAdd(&out[b * 2 + 0], sx);
            atomicAdd(&out[b * 2 + 1], sy);
        }
    }
}

// ---------------------------------------------------------------------------
// Launch: two kernels, single stream, graph-safe.
// Inputs (metadata order): feats(i32), tables(f32), W_small(f32),
//                          W_concat(f32), arch_weights(f32)
// ---------------------------------------------------------------------------
extern "C" void kernel_launch(void* const* d_in, const int* in_sizes, int n_in,
                              void* d_out, int out_size)
{
    const int*   feats   = (const int*)  d_in[0];
    const float* tables  = (const float*)d_in[1];
    const float* Wsmall  = (const float*)d_in[2];
    const float* Wconcat = (const float*)d_in[3];
    const float* aw      = (const float*)d_in[4];
    float*       out     = (float*)d_out;

    const int B = in_sizes[0] / N_COLS;   // 4096

    // host-side tables: triu pairs, then same-i pairing into items
    K1Tab k1t;
    K2Tab k2t;
    {
        uchar2 ij[N_PAIRS];
        int p = 0;
        for (int i = 0; i < N_COLS; ++i)
            for (int j = i + 1; j < N_COLS; ++j, ++p)
                ij[p] = make_uchar2((unsigned char)i, (unsigned char)j);
        for (int q = 0; q < N_PAIRS; ++q) k1t.ij[q] = ij[q];

        int m = 0;
        p = 0;
        for (int i = 0; i < N_COLS; ++i) {
            const int cnt = N_COLS - 1 - i;      // pairs in this i-row
            int t = 0;
            for (; t + 1 < cnt; t += 2, ++m) {   // merge consecutive j's
                k1t.bp[m]   = make_uchar2((unsigned char)(p + t), (unsigned char)(p + t + 1));
                k2t.cols[m] = make_uchar4((unsigned char)i, ij[p + t].y, ij[p + t + 1].y, 0);
            }
            if (t < cnt) {                       // leftover single
                k1t.bp[m]   = make_uchar2((unsigned char)(p + t), 255);
                k2t.cols[m] = make_uchar4((unsigned char)i, ij[p + t].y, ij[p + t].y, 0);
                ++m;
            }
            p += cnt;
        }
        // m == N_ITEMS == 121
    }

    build_lut_kernel<<<N_ITEMS, 512>>>(tables, Wsmall, Wconcat, aw,
                                       out, out_size, k1t);

    dim3 grid(NCHUNK, (B + 31) / 32);     // 8 x 128 = 1024 blocks, chunk-major
    accumulate_kernel<<<grid, 256>>>(feats, out, B, k2t);
}

// round 16
// speedup vs baseline: 1.1774x; 1.1774x over previous
#include <cuda_runtime.h>
#include <cuda_bf16.h>
#include <cstdint>

// Problem constants (fixed by the reference)
#define N_COLS  22
#define N_PAIRS 231
#define EMB     12
#define DVEC    64
#define N_PRIM  5
#define COMBO2  (EMB * EMB * 2)   // 288 floats per pair in the LUT
#define NCHUNK  8                 // pair-dimension split for kernel 2
#define CHUNKSZ ((N_PAIRS + NCHUNK - 1) / NCHUNK)   // 29

// Pair index table, computed on host, passed by value (constant bank)
struct PairTab { uchar2 ij[N_PAIRS]; };

// Scratch: precomputed per-pair lookup table T[p][fi][fj][o]  (266 KB)
__device__ __align__(16) float g_T[N_PAIRS * COMBO2];

// ---------------------------------------------------------------------------
// Kernel 1: warp-per-(p, fi), quarter-warp layout. No SMEM, no __syncthreads.
// Lane q=lane>>3 (quarter), ql=lane&7 holds dims 8ql..8ql+7 (two float4).
// Quarter q computes fj = 4t+q for t=0..2; 3-level shuffle reduce (xor 4,2,1).
// Zero-initializes out[], then signals PDL so kernel 2 can begin its preamble.
// ---------------------------------------------------------------------------
__global__ __launch_bounds__(256)
void build_lut_kernel(const float* __restrict__ tables,
                      const float* __restrict__ Wsmall,
                      const float* __restrict__ Wconcat,
                      const float* __restrict__ aw,
                      float* __restrict__ out, int outN,
                      const PairTab tab)
{
    // zero the output buffer (poisoned by harness)
    {
        const int gz = blockIdx.x * 256 + threadIdx.x;
        if (gz < outN) out[gz] = 0.0f;
    }

    // PDL: let the dependent grid (kernel 2) launch and run its preamble.
    // Its g_T/out accesses sit behind griddepcontrol.wait, which releases only
    // when this grid fully completes (memory visible). Must execute in every
    // CTA, before any early return.
    asm volatile("griddepcontrol.launch_dependents;" ::: "memory");

    const int gwarp = (blockIdx.x * 256 + threadIdx.x) >> 5;
    if (gwarp >= N_PAIRS * EMB) return;

    const int p    = gwarp / EMB;
    const int fi   = gwarp % EMB;
    const int lane = threadIdx.x & 31;
    const int q    = lane >> 3;          // quarter 0..3
    const int ql   = lane & 7;           // dim-octet within quarter

    const int i = tab.ij[p].x;
    const int j = tab.ij[p].y;

    // primitive via one ballot (arch_weights is exact one-hot 0/1)
    const bool hot = (lane < N_PRIM) && (__ldg(&aw[p * N_PRIM + lane]) > 0.5f);
    const int  k   = __ffs(__ballot_sync(0xffffffffu, hot)) - 1;

    const float4* __restrict__ t4 = (const float4*)tables;
    const float4 PiA = __ldg(&t4[(i * EMB + fi) * 16 + 2 * ql]);
    const float4 PiB = __ldg(&t4[(i * EMB + fi) * 16 + 2 * ql + 1]);

    float4 w0A, w0B, w1A, w1B;           // Q-side weights, o = 0 / 1
    float  pp0 = 0.0f, pp1 = 0.0f;       // reduced P-part for concat
    if (k == 4) {
        const float4* __restrict__ wc = (const float4*)(Wconcat + p * 2 * (2 * DVEC));
        const float4 a0A = __ldg(&wc[2 * ql]),      a0B = __ldg(&wc[2 * ql + 1]);      // o=0 P
        const float4 a1A = __ldg(&wc[32 + 2 * ql]), a1B = __ldg(&wc[33 + 2 * ql]);     // o=1 P
        w0A = __ldg(&wc[16 + 2 * ql]);  w0B = __ldg(&wc[17 + 2 * ql]);                 // o=0 Q
        w1A = __ldg(&wc[48 + 2 * ql]);  w1B = __ldg(&wc[49 + 2 * ql]);                 // o=1 Q
        pp0 = a0A.x * PiA.x + a0A.y * PiA.y + a0A.z * PiA.z + a0A.w * PiA.w
            + a0B.x * PiB.x + a0B.y * PiB.y + a0B.z * PiB.z + a0B.w * PiB.w;
        pp1 = a1A.x * PiA.x + a1A.y * PiA.y + a1A.z * PiA.z + a1A.w * PiA.w
            + a1B.x * PiB.x + a1B.y * PiB.y + a1B.z * PiB.z + a1B.w * PiB.w;
#pragma unroll
        for (int off = 4; off; off >>= 1) {
            pp0 += __shfl_xor_sync(0xffffffffu, pp0, off);
            pp1 += __shfl_xor_sync(0xffffffffu, pp1, off);
        }
    } else {
        const float4* __restrict__ ws = (const float4*)(Wsmall + (p * 4 + k) * 2 * DVEC);
        w0A = __ldg(&ws[2 * ql]);       w0B = __ldg(&ws[2 * ql + 1]);
        w1A = __ldg(&ws[16 + 2 * ql]);  w1B = __ldg(&ws[17 + 2 * ql]);
    }

    float2* __restrict__ T2 = (float2*)g_T;

#pragma unroll
    for (int t = 0; t < 3; ++t) {
        const int fj = t * 4 + q;
        const float4 QA = __ldg(&t4[(j * EMB + fj) * 16 + 2 * ql]);
        const float4 QB = __ldg(&t4[(j * EMB + fj) * 16 + 2 * ql + 1]);

        float4 zA, zB;
        if (k == 0)      { zA.x = PiA.x + QA.x; zA.y = PiA.y + QA.y; zA.z = PiA.z + QA.z; zA.w = PiA.w + QA.w;
                           zB.x = PiB.x + QB.x; zB.y = PiB.y + QB.y; zB.z = PiB.z + QB.z; zB.w = PiB.w + QB.w; }
        else if (k == 1) { zA.x = PiA.x * QA.x; zA.y = PiA.y * QA.y; zA.z = PiA.z * QA.z; zA.w = PiA.w * QA.w;
                           zB.x = PiB.x * QB.x; zB.y = PiB.y * QB.y; zB.z = PiB.z * QB.z; zB.w = PiB.w * QB.w; }
        else if (k == 2) { zA.x = fmaxf(PiA.x, QA.x); zA.y = fmaxf(PiA.y, QA.y); zA.z = fmaxf(PiA.z, QA.z); zA.w = fmaxf(PiA.w, QA.w);
                           zB.x = fmaxf(PiB.x, QB.x); zB.y = fmaxf(PiB.y, QB.y); zB.z = fmaxf(PiB.z, QB.z); zB.w = fmaxf(PiB.w, QB.w); }
        else if (k == 3) { zA.x = fminf(PiA.x, QA.x); zA.y = fminf(PiA.y, QA.y); zA.z = fminf(PiA.z, QA.z); zA.w = fminf(PiA.w, QA.w);
                           zB.x = fminf(PiB.x, QB.x); zB.y = fminf(PiB.y, QB.y); zB.z = fminf(PiB.z, QB.z); zB.w = fminf(PiB.w, QB.w); }
        else             { zA = QA; zB = QB; }   // concat: Q-part only

        float s0 = zA.x * w0A.x + zA.y * w0A.y + zA.z * w0A.z + zA.w * w0A.w
                 + zB.x * w0B.x + zB.y * w0B.y + zB.z * w0B.z + zB.w * w0B.w;
        float s1 = zA.x * w1A.x + zA.y * w1A.y + zA.z * w1A.z + zA.w * w1A.w
                 + zB.x * w1B.x + zB.y * w1B.y + zB.z * w1B.z + zB.w * w1B.w;
#pragma unroll
        for (int off = 4; off; off >>= 1) {
            s0 += __shfl_xor_sync(0xffffffffu, s0, off);
            s1 += __shfl_xor_sync(0xffffffffu, s1, off);
        }
        if (k == 4) { s0 += pp0; s1 += pp1; }

        if (ql == 0)
            T2[p * (EMB * EMB) + fi * EMB + fj] = make_float2(s0, s1);
    }
}

// ---------------------------------------------------------------------------
// Kernel 2: out[b, :] += sum_{p in chunk} T[p, f[i_p], f[j_p], :]
// grid = (NCHUNK, B/32), 256 threads (R12 winner). Chunk-major grid keeps L1
// chunk-affinity (stride 148 mod 8 = 4 -> each SM hosts chunks {c, c+4}).
// PDL: launches during kernel 1; stages feats (flat int4: 176 LDG.128, no
// div/mod) and syncs BEFORE griddepcontrol.wait, so startup+staging overlap
// kernel 1's compute. Gathers/atomics run after the wait. In-loop feats
// access shf[lane*22+c] is <=2-way bank conflicted (gcd(22,32)=2).
// ---------------------------------------------------------------------------
__global__ __launch_bounds__(256)
void accumulate_kernel(const int* __restrict__ feats,
                       float* __restrict__ out,
                       int B,
                       const PairTab tab)
{
    __shared__ int    shf[32 * N_COLS];      // flat 704 words
    __shared__ float2 shred[8][32];

    const int tid   = threadIdx.x;
    const int lane  = tid & 31;
    const int warp  = tid >> 5;
    const int bbase = blockIdx.y * 32;       // tile
    const int p0    = blockIdx.x * CHUNKSZ;  // chunk
    const int npair = min(N_PAIRS - p0, CHUNKSZ);

    // ---- preamble (overlaps kernel 1 under PDL): stage feats tile ----
    if (bbase + 32 <= B) {
        // fast path: one int4 per thread (704 words = 176 int4)
        const int4* __restrict__ src = (const int4*)(feats + bbase * N_COLS);
        if (tid < (32 * N_COLS) / 4)
            ((int4*)shf)[tid] = __ldg(&src[tid]);
    } else {
        for (int e = tid; e < 32 * N_COLS; e += 256) {
            const int b = bbase + e / N_COLS;
            shf[e] = (b < B) ? feats[b * N_COLS + (e % N_COLS)] : 0;
        }
    }
    __syncthreads();

    // ---- gate on kernel 1 completion (g_T + zeroed out visible) ----
    asm volatile("griddepcontrol.wait;" ::: "memory");

    const float2* __restrict__ T2 = (const float2*)g_T;
    float ax = 0.0f, ay = 0.0f;

    // warp w handles chunk-local pairs w, w+8, ... (<= 4 independent gathers)
#pragma unroll 4
    for (int t = warp; t < npair; t += 8) {
        const uchar2 ij = tab.ij[p0 + t];        // constant bank, uniform
        const int fi = shf[lane * N_COLS + ij.x];
        const int fj = shf[lane * N_COLS + ij.y];
        const float2 v = __ldg(&T2[(p0 + t) * (EMB * EMB) + fi * EMB + fj]);
        ax += v.x;
        ay += v.y;
    }

    shred[warp][lane] = make_float2(ax, ay);
    __syncthreads();

    if (warp == 0) {
        float sx = 0.0f, sy = 0.0f;
#pragma unroll
        for (int w = 0; w < 8; ++w) {
            const float2 s = shred[w][lane];
            sx += s.x;
            sy += s.y;
        }
        const int b = bbase + lane;
        if (b < B) {
            atomicAdd(&out[b * 2 + 0], sx);
            atomicAdd(&out[b * 2 + 1], sy);
        }
    }
}

// ---------------------------------------------------------------------------
// Launch: k1 normally; k2 via cudaLaunchKernelEx with programmatic stream
// serialization (PDL) so it launches while k1 is still running. Same stream,
// graph-capturable. Inputs: feats(i32), tables(f32), W_small, W_concat,
// arch_weights.
// ---------------------------------------------------------------------------
extern "C" void kernel_launch(void* const* d_in, const int* in_sizes, int n_in,
                              void* d_out, int out_size)
{
    const int*   feats   = (const int*)  d_in[0];
    const float* tables  = (const float*)d_in[1];
    const float* Wsmall  = (const float*)d_in[2];
    const float* Wconcat = (const float*)d_in[3];
    const float* aw      = (const float*)d_in[4];
    float*       out     = (float*)d_out;

    const int B = in_sizes[0] / N_COLS;   // 4096

    // host-side triu(N_COLS, 1) pair table -> constant-bank kernel param
    PairTab tab;
    {
        int p = 0;
        for (int i = 0; i < N_COLS; ++i)
            for (int j = i + 1; j < N_COLS; ++j, ++p)
                tab.ij[p] = make_uchar2((unsigned char)i, (unsigned char)j);
    }

    const int k1_blocks = (N_PAIRS * EMB * 32 + 255) / 256;   // 347
    build_lut_kernel<<<k1_blocks, 256>>>(tables, Wsmall, Wconcat, aw,
                                         out, out_size, tab);

    cudaLaunchConfig_t cfg = {};
    cfg.gridDim  = dim3(NCHUNK, (B + 31) / 32, 1);   // 8 x 128, chunk-major
    cfg.blockDim = dim3(256, 1, 1);
    cfg.stream   = 0;
    cudaLaunchAttribute attr[1];
    attr[0].id = cudaLaunchAttributeProgrammaticStreamSerialization;
    attr[0].val.programmaticStreamSerializationAllowed = 1;
    cfg.attrs    = attr;
    cfg.numAttrs = 1;
    cudaLaunchKernelEx(&cfg, accumulate_kernel, feats, out, B, tab);
}